// round 1
// baseline (speedup 1.0000x reference)
#include <cuda_runtime.h>

#define BB 2
#define LL 2048
#define DD 1024
#define NS 16
#define RR 64
#define EE 96
#define NC 32
#define LC 64   /* LL / NC */

// ---------------- scratch (static device globals; no allocation) ----------------
__device__ float  g_xdbl[BB*LL*EE];          // (b,l,96): [0:64)=dt_in, [64:80)=B, [80:96)=C
__device__ float  g_dt[BB*LL*DD];            // softplus(dt_proj) full
__device__ float4 g_P  [NC*BB*DD*NS/4];      // per-chunk cumulative dA product
__device__ float4 g_S  [NC*BB*DD*NS/4];      // per-chunk local final state (h0=0)
__device__ float4 g_hin[NC*BB*DD*NS/4];      // corrected chunk-entry state

// ---------------- generic NT GEMM: C[m][n] = sum_k A[m][k]*B[n][k] ----------------
template<int BM,int BN,int BK,int TM,int TN,bool SP>
__global__ void __launch_bounds__(256) gemm_nt(
    const float* __restrict__ A, int lda,
    const float* __restrict__ Bm, int ldb,
    float* __restrict__ Cm, int ldc,
    int K, const float* __restrict__ bias)
{
    __shared__ float As[BK][BM+1];
    __shared__ float Bs[BK][BN+1];
    const int t  = threadIdx.x;
    const int tx = t % (BN/TN);
    const int ty = t / (BN/TN);
    const int m0 = blockIdx.x * BM;
    const int n0 = blockIdx.y * BN;

    float acc[TM][TN];
    #pragma unroll
    for (int i=0;i<TM;i++)
        #pragma unroll
        for (int j=0;j<TN;j++) acc[i][j] = 0.f;

    for (int k0 = 0; k0 < K; k0 += BK) {
        #pragma unroll
        for (int i = 0; i < BM*BK/256; i++) {
            int lin = t + i*256;
            int kk = lin % BK, r = lin / BK;
            As[kk][r] = A[(m0+r)*lda + k0 + kk];
        }
        #pragma unroll
        for (int i = 0; i < BN*BK/256; i++) {
            int lin = t + i*256;
            int kk = lin % BK, cc = lin / BK;
            Bs[kk][cc] = Bm[(n0+cc)*ldb + k0 + kk];
        }
        __syncthreads();
        #pragma unroll
        for (int kk = 0; kk < BK; kk++) {
            float a[TM], b[TN];
            #pragma unroll
            for (int i=0;i<TM;i++) a[i] = As[kk][ty*TM+i];
            #pragma unroll
            for (int j=0;j<TN;j++) b[j] = Bs[kk][tx*TN+j];
            #pragma unroll
            for (int i=0;i<TM;i++)
                #pragma unroll
                for (int j=0;j<TN;j++)
                    acc[i][j] = fmaf(a[i], b[j], acc[i][j]);
        }
        __syncthreads();
    }

    #pragma unroll
    for (int i=0;i<TM;i++) {
        int m = m0 + ty*TM + i;
        #pragma unroll
        for (int j=0;j<TN;j++) {
            int n = n0 + tx*TN + j;
            float v = acc[i][j];
            if (SP) {
                v += bias[n];
                v = (v > 20.f) ? v : log1pf(__expf(v));
            }
            Cm[m*ldc + n] = v;
        }
    }
}

// ---------------- helpers: power ladder e^(n+1) for n=0..15 ----------------
__device__ __forceinline__ void pow_ladder(float e1, float* dA) {
    float e2 = e1*e1, e4 = e2*e2, e8 = e4*e4;
    dA[0]=e1;        dA[1]=e2;        dA[2]=e2*e1;     dA[3]=e4;
    dA[4]=e4*e1;     dA[5]=e4*e2;     dA[6]=e4*dA[2];  dA[7]=e8;
    dA[8]=e8*e1;     dA[9]=e8*e2;     dA[10]=e8*dA[2]; dA[11]=e8*e4;
    dA[12]=e8*dA[4]; dA[13]=e8*dA[5]; dA[14]=e8*dA[6]; dA[15]=e8*e8;
}

// ---------------- pass 1: per-chunk local scan, emit (P, S) ----------------
__global__ void __launch_bounds__(128) scan_pass1(
    const float* __restrict__ x, const float* __restrict__ A_log)
{
    __shared__ alignas(16) float Bsh[LC*NS];
    const int tid = threadIdx.x;
    const int d = blockIdx.x*128 + tid;
    const int b = blockIdx.y;
    const int c = blockIdx.z;
    const int l0 = c*LC;

    for (int i = tid; i < LC*NS; i += 128) {
        int l = i >> 4, n = i & 15;
        Bsh[i] = g_xdbl[(b*LL + l0 + l)*EE + RR + n];
    }
    __syncthreads();

    float an[NS];
    #pragma unroll
    for (int n=0;n<NS;n++) an[n] = -__expf(A_log[d*NS+n]);
    const float a0 = an[0];
    bool chain = true;
    #pragma unroll
    for (int n=1;n<NS;n++)
        chain = chain && (fabsf(an[n] - (float)(n+1)*a0) <= 2e-5f*(float)(n+1));

    float h[NS];
    #pragma unroll
    for (int n=0;n<NS;n++) h[n] = 0.f;

    const float4* Bs4 = reinterpret_cast<const float4*>(Bsh);
    const float* dtp = g_dt + (size_t)(b*LL + l0)*DD + d;
    const float* xp  = x    + (size_t)(b*LL + l0)*DD + d;

    float P[NS];
    if (chain) {
        float E = 1.f;
        for (int l = 0; l < LC; l++) {
            float dtv = dtp[l*DD];
            float xv  = xp[l*DD];
            float dtx = dtv * xv;
            float e1 = __expf(dtv * a0);
            E *= e1;
            float dA[NS];
            pow_ladder(e1, dA);
            float4 b0 = Bs4[l*4], b1 = Bs4[l*4+1], b2 = Bs4[l*4+2], b3 = Bs4[l*4+3];
            float bv[NS] = {b0.x,b0.y,b0.z,b0.w, b1.x,b1.y,b1.z,b1.w,
                            b2.x,b2.y,b2.z,b2.w, b3.x,b3.y,b3.z,b3.w};
            #pragma unroll
            for (int n=0;n<NS;n++) h[n] = fmaf(dA[n], h[n], dtx*bv[n]);
        }
        pow_ladder(E, P);
    } else {
        #pragma unroll
        for (int n=0;n<NS;n++) P[n] = 1.f;
        for (int l = 0; l < LC; l++) {
            float dtv = dtp[l*DD];
            float xv  = xp[l*DD];
            float dtx = dtv * xv;
            float4 b0 = Bs4[l*4], b1 = Bs4[l*4+1], b2 = Bs4[l*4+2], b3 = Bs4[l*4+3];
            float bv[NS] = {b0.x,b0.y,b0.z,b0.w, b1.x,b1.y,b1.z,b1.w,
                            b2.x,b2.y,b2.z,b2.w, b3.x,b3.y,b3.z,b3.w};
            #pragma unroll
            for (int n=0;n<NS;n++) {
                float dA = __expf(dtv * an[n]);
                P[n] *= dA;
                h[n] = fmaf(dA, h[n], dtx*bv[n]);
            }
        }
    }

    const int base4 = ((c*BB + b)*DD + d)*4;   // index into float4 arrays
    #pragma unroll
    for (int q=0;q<4;q++) {
        g_P[base4+q] = make_float4(P[q*4],P[q*4+1],P[q*4+2],P[q*4+3]);
        g_S[base4+q] = make_float4(h[q*4],h[q*4+1],h[q*4+2],h[q*4+3]);
    }
}

// ---------------- pass 2: sequential chunk combine (tiny) ----------------
__global__ void __launch_bounds__(256) scan_pass2()
{
    const int i = blockIdx.x*256 + threadIdx.x;     // over BB*DD*NS = 32768
    const float* Pf = (const float*)g_P;
    const float* Sf = (const float*)g_S;
    float* Hf = (float*)g_hin;
    float h = 0.f;
    #pragma unroll
    for (int c = 0; c < NC; c++) {
        int idx = c*(BB*DD*NS) + i;
        Hf[idx] = h;
        h = fmaf(Pf[idx], h, Sf[idx]);
    }
}

// ---------------- pass 3: final scan with corrected h0, emit y ----------------
__global__ void __launch_bounds__(128) scan_pass3(
    const float* __restrict__ x, const float* __restrict__ A_log,
    const float* __restrict__ Dparam, float* __restrict__ out)
{
    __shared__ alignas(16) float Bsh[LC*NS];
    __shared__ alignas(16) float Csh[LC*NS];
    const int tid = threadIdx.x;
    const int d = blockIdx.x*128 + tid;
    const int b = blockIdx.y;
    const int c = blockIdx.z;
    const int l0 = c*LC;

    for (int i = tid; i < LC*NS; i += 128) {
        int l = i >> 4, n = i & 15;
        int base = (b*LL + l0 + l)*EE + RR;
        Bsh[i] = g_xdbl[base + n];
        Csh[i] = g_xdbl[base + NS + n];
    }
    __syncthreads();

    float an[NS];
    #pragma unroll
    for (int n=0;n<NS;n++) an[n] = -__expf(A_log[d*NS+n]);
    const float a0 = an[0];
    bool chain = true;
    #pragma unroll
    for (int n=1;n<NS;n++)
        chain = chain && (fabsf(an[n] - (float)(n+1)*a0) <= 2e-5f*(float)(n+1));

    float h[NS];
    {
        const int base4 = ((c*BB + b)*DD + d)*4;
        #pragma unroll
        for (int q=0;q<4;q++) {
            float4 v = g_hin[base4+q];
            h[q*4]=v.x; h[q*4+1]=v.y; h[q*4+2]=v.z; h[q*4+3]=v.w;
        }
    }

    const float Dp = Dparam[d];
    const float* dtp = g_dt + (size_t)(b*LL + l0)*DD + d;
    const float* xp  = x    + (size_t)(b*LL + l0)*DD + d;
    float* yp        = out  + (size_t)(b*LL + l0)*DD + d;
    const float4* Bs4 = reinterpret_cast<const float4*>(Bsh);
    const float4* Cs4 = reinterpret_cast<const float4*>(Csh);

    if (chain) {
        for (int l = 0; l < LC; l++) {
            float dtv = dtp[l*DD];
            float xv  = xp[l*DD];
            float dtx = dtv * xv;
            float e1 = __expf(dtv * a0);
            float dA[NS];
            pow_ladder(e1, dA);
            float4 b0 = Bs4[l*4], b1 = Bs4[l*4+1], b2 = Bs4[l*4+2], b3 = Bs4[l*4+3];
            float bv[NS] = {b0.x,b0.y,b0.z,b0.w, b1.x,b1.y,b1.z,b1.w,
                            b2.x,b2.y,b2.z,b2.w, b3.x,b3.y,b3.z,b3.w};
            #pragma unroll
            for (int n=0;n<NS;n++) h[n] = fmaf(dA[n], h[n], dtx*bv[n]);
            float4 c0 = Cs4[l*4], c1 = Cs4[l*4+1], c2 = Cs4[l*4+2], c3 = Cs4[l*4+3];
            float ya = fmaf(h[0],c0.x, fmaf(h[1],c0.y, fmaf(h[2],c0.z, h[3]*c0.w)));
            float yb = fmaf(h[4],c1.x, fmaf(h[5],c1.y, fmaf(h[6],c1.z, h[7]*c1.w)));
            float yc = fmaf(h[8],c2.x, fmaf(h[9],c2.y, fmaf(h[10],c2.z, h[11]*c2.w)));
            float yd = fmaf(h[12],c3.x, fmaf(h[13],c3.y, fmaf(h[14],c3.z, h[15]*c3.w)));
            yp[l*DD] = fmaf(xv, Dp, (ya+yb)+(yc+yd));
        }
    } else {
        for (int l = 0; l < LC; l++) {
            float dtv = dtp[l*DD];
            float xv  = xp[l*DD];
            float dtx = dtv * xv;
            float4 b0 = Bs4[l*4], b1 = Bs4[l*4+1], b2 = Bs4[l*4+2], b3 = Bs4[l*4+3];
            float bv[NS] = {b0.x,b0.y,b0.z,b0.w, b1.x,b1.y,b1.z,b1.w,
                            b2.x,b2.y,b2.z,b2.w, b3.x,b3.y,b3.z,b3.w};
            #pragma unroll
            for (int n=0;n<NS;n++) {
                float dA = __expf(dtv * an[n]);
                h[n] = fmaf(dA, h[n], dtx*bv[n]);
            }
            float4 c0 = Cs4[l*4], c1 = Cs4[l*4+1], c2 = Cs4[l*4+2], c3 = Cs4[l*4+3];
            float ya = fmaf(h[0],c0.x, fmaf(h[1],c0.y, fmaf(h[2],c0.z, h[3]*c0.w)));
            float yb = fmaf(h[4],c1.x, fmaf(h[5],c1.y, fmaf(h[6],c1.z, h[7]*c1.w)));
            float yc = fmaf(h[8],c2.x, fmaf(h[9],c2.y, fmaf(h[10],c2.z, h[11]*c2.w)));
            float yd = fmaf(h[12],c3.x, fmaf(h[13],c3.y, fmaf(h[14],c3.z, h[15]*c3.w)));
            yp[l*DD] = fmaf(xv, Dp, (ya+yb)+(yc+yd));
        }
    }
}

// ---------------- launch ----------------
extern "C" void kernel_launch(void* const* d_in, const int* in_sizes, int n_in,
                              void* d_out, int out_size) {
    const float* x     = (const float*)d_in[0];
    const float* Wx    = (const float*)d_in[1];
    const float* Wdt   = (const float*)d_in[2];
    const float* bdt   = (const float*)d_in[3];
    const float* A_log = (const float*)d_in[4];
    const float* Dp    = (const float*)d_in[5];
    float* out = (float*)d_out;

    float *p_xdbl = nullptr, *p_dt = nullptr;
    cudaGetSymbolAddress((void**)&p_xdbl, g_xdbl);
    cudaGetSymbolAddress((void**)&p_dt,   g_dt);

    // GEMM1: x_dbl(4096,96) = X(4096,1024) @ Wx^T
    gemm_nt<32,96,32,2,6,false><<<dim3(BB*LL/32, 1), 256>>>(
        x, DD, Wx, DD, p_xdbl, EE, DD, nullptr);

    // GEMM2 + softplus: dt(4096,1024) = x_dbl[:, :64] @ Wdt^T + bdt
    gemm_nt<64,64,64,4,4,true><<<dim3(BB*LL/64, DD/64), 256>>>(
        p_xdbl, EE, Wdt, RR, p_dt, DD, RR, bdt);

    // chunked selective scan
    scan_pass1<<<dim3(DD/128, BB, NC), 128>>>(x, A_log);
    scan_pass2<<<BB*DD*NS/256, 256>>>();
    scan_pass3<<<dim3(DD/128, BB, NC), 128>>>(x, A_log, Dp, out);
}

// round 2
// speedup vs baseline: 1.2325x; 1.2325x over previous
#include <cuda_runtime.h>

#define BB 2
#define LL 2048
#define DD 1024
#define NS 16
#define RR 64
#define EE 96
#define NC 32
#define LC 64   /* LL / NC */

typedef unsigned long long u64;

// ---------------- packed f32x2 helpers ----------------
__device__ __forceinline__ u64 pk2(float x, float y) {
    u64 r; asm("mov.b64 %0,{%1,%2};" : "=l"(r) : "f"(x), "f"(y)); return r;
}
__device__ __forceinline__ float2 upk(u64 v) {
    float2 f; asm("mov.b64 {%0,%1},%2;" : "=f"(f.x), "=f"(f.y) : "l"(v)); return f;
}
__device__ __forceinline__ u64 fma2_(u64 a, u64 b, u64 c) {
    u64 d; asm("fma.rn.f32x2 %0,%1,%2,%3;" : "=l"(d) : "l"(a), "l"(b), "l"(c)); return d;
}
__device__ __forceinline__ u64 mul2_(u64 a, u64 b) {
    u64 d; asm("mul.rn.f32x2 %0,%1,%2;" : "=l"(d) : "l"(a), "l"(b)); return d;
}

// ---------------- scratch ----------------
__device__ float g_part[8 * BB*LL * EE];     // GEMM1 split-K partials (12.6MB)
__device__ float g_xdbl[BB*LL*EE];           // (b,l,96): [0:64)=dt_in, [64:80)=B, [80:96)=C
__device__ float g_dt[BB*LL*DD];             // softplus(dt_proj)
__device__ u64   g_P  [NC*BB*DD*8];          // per-chunk cumulative dA product (packed pairs)
__device__ u64   g_S  [NC*BB*DD*8];          // per-chunk local final state
__device__ u64   g_hin[NC*BB*DD*8];          // corrected chunk-entry state

// =========================================================================
// GEMM1 (split-K partials): part[ks][m][n] = sum_{k in slice} X[m][k]*Wx[n][k]
// BM=64, BN=96, BK=32, TM=8, TN=8, 96 threads, 8 k-slices of 128
// =========================================================================
#define G1_BM 64
#define G1_BN 96
#define G1_BK 32
#define G1_KC 128

__global__ void __launch_bounds__(96) gemm1_partial(
    const float* __restrict__ X, const float* __restrict__ Wx)
{
    __shared__ float As[G1_BK][G1_BM + 4];
    __shared__ float Bs[G1_BK][G1_BN + 4];
    const int t  = threadIdx.x;
    const int tx = t % 12;            // n-group (12 * TN=8 = 96)
    const int ty = t / 12;            // m-group (8  * TM=8 = 64)
    const int m0 = blockIdx.x * G1_BM;
    const int ks = blockIdx.y;

    u64 acc[8][4];
    #pragma unroll
    for (int i = 0; i < 8; i++)
        #pragma unroll
        for (int j = 0; j < 4; j++) acc[i][j] = 0ull;

    for (int kt = 0; kt < G1_KC / G1_BK; kt++) {
        const int k0 = ks * G1_KC + kt * G1_BK;
        // A tile: 64x32 = 512 float4
        for (int i = t; i < 512; i += 96) {
            int row = i >> 3, q = i & 7;
            float4 v = *(const float4*)&X[(m0 + row) * DD + k0 + q * 4];
            As[q*4+0][row] = v.x; As[q*4+1][row] = v.y;
            As[q*4+2][row] = v.z; As[q*4+3][row] = v.w;
        }
        // B tile: 96x32 = 768 float4
        for (int i = t; i < 768; i += 96) {
            int n = i >> 3, q = i & 7;
            float4 v = *(const float4*)&Wx[n * DD + k0 + q * 4];
            Bs[q*4+0][n] = v.x; Bs[q*4+1][n] = v.y;
            Bs[q*4+2][n] = v.z; Bs[q*4+3][n] = v.w;
        }
        __syncthreads();
        #pragma unroll
        for (int kk = 0; kk < G1_BK; kk++) {
            float4 av0 = *(const float4*)&As[kk][ty * 8];
            float4 av1 = *(const float4*)&As[kk][ty * 8 + 4];
            ulonglong2 bq0 = *(const ulonglong2*)&Bs[kk][tx * 8];
            ulonglong2 bq1 = *(const ulonglong2*)&Bs[kk][tx * 8 + 4];
            u64 b2[4] = {bq0.x, bq0.y, bq1.x, bq1.y};
            float a[8] = {av0.x, av0.y, av0.z, av0.w, av1.x, av1.y, av1.z, av1.w};
            #pragma unroll
            for (int i = 0; i < 8; i++) {
                u64 a2 = pk2(a[i], a[i]);
                #pragma unroll
                for (int j = 0; j < 4; j++)
                    acc[i][j] = fma2_(a2, b2[j], acc[i][j]);
            }
        }
        __syncthreads();
    }

    float* outp = g_part + (size_t)ks * (BB*LL*EE);
    #pragma unroll
    for (int i = 0; i < 8; i++) {
        int m = m0 + ty * 8 + i;
        float2 p0 = upk(acc[i][0]), p1 = upk(acc[i][1]);
        float2 p2 = upk(acc[i][2]), p3 = upk(acc[i][3]);
        *(float4*)&outp[m * EE + tx * 8]     = make_float4(p0.x, p0.y, p1.x, p1.y);
        *(float4*)&outp[m * EE + tx * 8 + 4] = make_float4(p2.x, p2.y, p3.x, p3.y);
    }
}

// reduce 8 partials -> g_xdbl (393216 floats = 98304 float4)
__global__ void __launch_bounds__(256) gemm1_reduce()
{
    const int i = blockIdx.x * 256 + threadIdx.x;      // < 98304
    const float4* p = (const float4*)g_part;
    float4 s = p[i];
    #pragma unroll
    for (int ks = 1; ks < 8; ks++) {
        float4 v = p[ks * 98304 + i];
        s.x += v.x; s.y += v.y; s.z += v.z; s.w += v.w;
    }
    ((float4*)g_xdbl)[i] = s;
}

// =========================================================================
// GEMM2 + softplus: dt[m][n] = softplus(sum_k xdbl[m][k]*Wdt[n][k] + bdt[n])
// BM=64, BN=128, BK=32, TM=8, TN=8, 128 threads
// =========================================================================
__global__ void __launch_bounds__(128) gemm2_softplus(
    const float* __restrict__ Wdt, const float* __restrict__ bdt)
{
    __shared__ float As[32][64 + 4];
    __shared__ float Bs[32][128 + 4];
    const int t  = threadIdx.x;
    const int tx = t % 16;            // n-group (16 * 8 = 128)
    const int ty = t / 16;            // m-group (8 * 8 = 64)
    const int m0 = blockIdx.x * 64;
    const int n0 = blockIdx.y * 128;

    u64 acc[8][4];
    #pragma unroll
    for (int i = 0; i < 8; i++)
        #pragma unroll
        for (int j = 0; j < 4; j++) acc[i][j] = 0ull;

    for (int kt = 0; kt < 2; kt++) {
        const int k0 = kt * 32;
        // A tile: 64x32 = 512 float4 (from g_xdbl cols [0,64))
        for (int i = t; i < 512; i += 128) {
            int row = i >> 3, q = i & 7;
            float4 v = *(const float4*)&g_xdbl[(m0 + row) * EE + k0 + q * 4];
            As[q*4+0][row] = v.x; As[q*4+1][row] = v.y;
            As[q*4+2][row] = v.z; As[q*4+3][row] = v.w;
        }
        // B tile: 128x32 = 1024 float4
        for (int i = t; i < 1024; i += 128) {
            int n = i >> 3, q = i & 7;
            float4 v = *(const float4*)&Wdt[(n0 + n) * RR + k0 + q * 4];
            Bs[q*4+0][n] = v.x; Bs[q*4+1][n] = v.y;
            Bs[q*4+2][n] = v.z; Bs[q*4+3][n] = v.w;
        }
        __syncthreads();
        #pragma unroll
        for (int kk = 0; kk < 32; kk++) {
            float4 av0 = *(const float4*)&As[kk][ty * 8];
            float4 av1 = *(const float4*)&As[kk][ty * 8 + 4];
            ulonglong2 bq0 = *(const ulonglong2*)&Bs[kk][tx * 8];
            ulonglong2 bq1 = *(const ulonglong2*)&Bs[kk][tx * 8 + 4];
            u64 b2[4] = {bq0.x, bq0.y, bq1.x, bq1.y};
            float a[8] = {av0.x, av0.y, av0.z, av0.w, av1.x, av1.y, av1.z, av1.w};
            #pragma unroll
            for (int i = 0; i < 8; i++) {
                u64 a2 = pk2(a[i], a[i]);
                #pragma unroll
                for (int j = 0; j < 4; j++)
                    acc[i][j] = fma2_(a2, b2[j], acc[i][j]);
            }
        }
        __syncthreads();
    }

    float4 bi0 = *(const float4*)&bdt[n0 + tx * 8];
    float4 bi1 = *(const float4*)&bdt[n0 + tx * 8 + 4];
    float bi[8] = {bi0.x, bi0.y, bi0.z, bi0.w, bi1.x, bi1.y, bi1.z, bi1.w};
    #pragma unroll
    for (int i = 0; i < 8; i++) {
        int m = m0 + ty * 8 + i;
        float2 p[4] = {upk(acc[i][0]), upk(acc[i][1]), upk(acc[i][2]), upk(acc[i][3])};
        float v[8] = {p[0].x, p[0].y, p[1].x, p[1].y, p[2].x, p[2].y, p[3].x, p[3].y};
        #pragma unroll
        for (int j = 0; j < 8; j++) {
            float w = v[j] + bi[j];
            v[j] = (w > 20.f) ? w : log1pf(__expf(w));
        }
        *(float4*)&g_dt[m * DD + n0 + tx * 8]     = make_float4(v[0], v[1], v[2], v[3]);
        *(float4*)&g_dt[m * DD + n0 + tx * 8 + 4] = make_float4(v[4], v[5], v[6], v[7]);
    }
}

// ---------------- power ladders ----------------
__device__ __forceinline__ void pow_ladder(float e1, float* dA) {
    float e2 = e1*e1, e4 = e2*e2, e8 = e4*e4;
    dA[0]=e1;        dA[1]=e2;        dA[2]=e2*e1;     dA[3]=e4;
    dA[4]=e4*e1;     dA[5]=e4*e2;     dA[6]=e4*dA[2];  dA[7]=e8;
    dA[8]=e8*e1;     dA[9]=e8*e2;     dA[10]=e8*dA[2]; dA[11]=e8*e4;
    dA[12]=e8*dA[4]; dA[13]=e8*dA[5]; dA[14]=e8*dA[6]; dA[15]=e8*e8;
}
// packed ladder: dA2[k] = (e1^(2k+1), e1^(2k+2))
__device__ __forceinline__ void pow_ladder2(float e1, u64* dA2) {
    float e2 = e1*e1, e4 = e2*e2, e8 = e4*e4;
    u64 d01 = pk2(e1, e2);
    u64 s2 = pk2(e2, e2), s4 = pk2(e4, e4), s8 = pk2(e8, e8);
    dA2[0] = d01;
    dA2[1] = mul2_(d01, s2);
    dA2[2] = mul2_(d01, s4);
    dA2[3] = mul2_(dA2[1], s4);
    dA2[4] = mul2_(d01, s8);
    dA2[5] = mul2_(dA2[1], s8);
    dA2[6] = mul2_(dA2[2], s8);
    dA2[7] = mul2_(dA2[3], s8);
}

// ---------------- pass 1: per-chunk local scan, emit (P, S) ----------------
__global__ void __launch_bounds__(128) scan_pass1(
    const float* __restrict__ x, const float* __restrict__ A_log)
{
    __shared__ alignas(16) float Bsh[LC*NS];
    const int tid = threadIdx.x;
    const int d = blockIdx.x*128 + tid;
    const int b = blockIdx.y;
    const int c = blockIdx.z;
    const int l0 = c*LC;

    for (int i = tid; i < LC*NS; i += 128) {
        int l = i >> 4, n = i & 15;
        Bsh[i] = g_xdbl[(b*LL + l0 + l)*EE + RR + n];
    }
    __syncthreads();

    float an[NS];
    #pragma unroll
    for (int n=0;n<NS;n++) an[n] = -__expf(A_log[d*NS+n]);
    const float a0 = an[0];
    bool chain = true;
    #pragma unroll
    for (int n=1;n<NS;n++)
        chain = chain && (fabsf(an[n] - (float)(n+1)*a0) <= 2e-5f*(float)(n+1));

    const float* dtp = g_dt + (size_t)(b*LL + l0)*DD + d;
    const float* xp  = x    + (size_t)(b*LL + l0)*DD + d;
    const int base8 = ((c*BB + b)*DD + d)*8;

    if (chain) {
        u64 h2[8];
        #pragma unroll
        for (int k=0;k<8;k++) h2[k] = 0ull;
        float E = 1.f;
        for (int l = 0; l < LC; l++) {
            float dtv = dtp[l*DD];
            float xv  = xp[l*DD];
            u64 dtx2 = pk2(dtv*xv, dtv*xv);
            float e1 = __expf(dtv * a0);
            E *= e1;
            u64 dA2[8];
            pow_ladder2(e1, dA2);
            const u64* Bp = (const u64*)(Bsh + l*NS);
            #pragma unroll
            for (int k=0;k<8;k++)
                h2[k] = fma2_(dA2[k], h2[k], mul2_(dtx2, Bp[k]));
        }
        u64 P2[8];
        pow_ladder2(E, P2);
        #pragma unroll
        for (int k=0;k<8;k++) { g_P[base8+k] = P2[k]; g_S[base8+k] = h2[k]; }
    } else {
        float h[NS], P[NS];
        #pragma unroll
        for (int n=0;n<NS;n++) { h[n]=0.f; P[n]=1.f; }
        for (int l = 0; l < LC; l++) {
            float dtv = dtp[l*DD];
            float dtx = dtv * xp[l*DD];
            #pragma unroll
            for (int n=0;n<NS;n++) {
                float dA = __expf(dtv * an[n]);
                P[n] *= dA;
                h[n] = fmaf(dA, h[n], dtx*Bsh[l*NS+n]);
            }
        }
        #pragma unroll
        for (int k=0;k<8;k++) { g_P[base8+k] = pk2(P[2*k],P[2*k+1]); g_S[base8+k] = pk2(h[2*k],h[2*k+1]); }
    }
}

// ---------------- pass 2: sequential chunk combine ----------------
__global__ void __launch_bounds__(256) scan_pass2()
{
    const int i = blockIdx.x*256 + threadIdx.x;     // over BB*DD*NS = 32768
    const float* Pf = (const float*)g_P;
    const float* Sf = (const float*)g_S;
    float* Hf = (float*)g_hin;
    float h = 0.f;
    #pragma unroll
    for (int c = 0; c < NC; c++) {
        int idx = c*(BB*DD*NS) + i;
        Hf[idx] = h;
        h = fmaf(Pf[idx], h, Sf[idx]);
    }
}

// ---------------- pass 3: final scan with corrected h0, emit y ----------------
__global__ void __launch_bounds__(128) scan_pass3(
    const float* __restrict__ x, const float* __restrict__ A_log,
    const float* __restrict__ Dparam, float* __restrict__ out)
{
    __shared__ alignas(16) float Bsh[LC*NS];
    __shared__ alignas(16) float Csh[LC*NS];
    const int tid = threadIdx.x;
    const int d = blockIdx.x*128 + tid;
    const int b = blockIdx.y;
    const int c = blockIdx.z;
    const int l0 = c*LC;

    for (int i = tid; i < LC*NS; i += 128) {
        int l = i >> 4, n = i & 15;
        int base = (b*LL + l0 + l)*EE + RR;
        Bsh[i] = g_xdbl[base + n];
        Csh[i] = g_xdbl[base + NS + n];
    }
    __syncthreads();

    float an[NS];
    #pragma unroll
    for (int n=0;n<NS;n++) an[n] = -__expf(A_log[d*NS+n]);
    const float a0 = an[0];
    bool chain = true;
    #pragma unroll
    for (int n=1;n<NS;n++)
        chain = chain && (fabsf(an[n] - (float)(n+1)*a0) <= 2e-5f*(float)(n+1));

    const int base8 = ((c*BB + b)*DD + d)*8;
    const float Dp = Dparam[d];
    const float* dtp = g_dt + (size_t)(b*LL + l0)*DD + d;
    const float* xp  = x    + (size_t)(b*LL + l0)*DD + d;
    float* yp        = out  + (size_t)(b*LL + l0)*DD + d;

    if (chain) {
        u64 h2[8];
        #pragma unroll
        for (int k=0;k<8;k++) h2[k] = g_hin[base8+k];
        for (int l = 0; l < LC; l++) {
            float dtv = dtp[l*DD];
            float xv  = xp[l*DD];
            u64 dtx2 = pk2(dtv*xv, dtv*xv);
            float e1 = __expf(dtv * a0);
            u64 dA2[8];
            pow_ladder2(e1, dA2);
            const u64* Bp = (const u64*)(Bsh + l*NS);
            const u64* Cp = (const u64*)(Csh + l*NS);
            u64 y2a = 0ull, y2b = 0ull;
            #pragma unroll
            for (int k=0;k<8;k+=2) {
                h2[k]   = fma2_(dA2[k],   h2[k],   mul2_(dtx2, Bp[k]));
                h2[k+1] = fma2_(dA2[k+1], h2[k+1], mul2_(dtx2, Bp[k+1]));
                y2a = fma2_(h2[k],   Cp[k],   y2a);
                y2b = fma2_(h2[k+1], Cp[k+1], y2b);
            }
            float2 ya = upk(y2a), yb = upk(y2b);
            yp[l*DD] = fmaf(xv, Dp, (ya.x+ya.y)+(yb.x+yb.y));
        }
    } else {
        float h[NS];
        #pragma unroll
        for (int k=0;k<8;k++) { float2 v = upk(g_hin[base8+k]); h[2*k]=v.x; h[2*k+1]=v.y; }
        for (int l = 0; l < LC; l++) {
            float dtv = dtp[l*DD];
            float xv  = xp[l*DD];
            float dtx = dtv * xv;
            float y = 0.f;
            #pragma unroll
            for (int n=0;n<NS;n++) {
                float dA = __expf(dtv * an[n]);
                h[n] = fmaf(dA, h[n], dtx*Bsh[l*NS+n]);
                y = fmaf(h[n], Csh[l*NS+n], y);
            }
            yp[l*DD] = fmaf(xv, Dp, y);
        }
    }
}

// ---------------- launch ----------------
extern "C" void kernel_launch(void* const* d_in, const int* in_sizes, int n_in,
                              void* d_out, int out_size) {
    const float* x     = (const float*)d_in[0];
    const float* Wx    = (const float*)d_in[1];
    const float* Wdt   = (const float*)d_in[2];
    const float* bdt   = (const float*)d_in[3];
    const float* A_log = (const float*)d_in[4];
    const float* Dp    = (const float*)d_in[5];
    float* out = (float*)d_out;

    // GEMM1 split-K: 64 m-blocks x 8 k-slices
    gemm1_partial<<<dim3(BB*LL/G1_BM, 8), 96>>>(x, Wx);
    gemm1_reduce<<<BB*LL*EE/4/256, 256>>>();

    // GEMM2 + softplus
    gemm2_softplus<<<dim3(BB*LL/64, DD/128), 128>>>(Wdt, bdt);

    // chunked selective scan
    scan_pass1<<<dim3(DD/128, BB, NC), 128>>>(x, A_log);
    scan_pass2<<<BB*DD*NS/256, 256>>>();
    scan_pass3<<<dim3(DD/128, BB, NC), 128>>>(x, A_log, Dp, out);
}